// round 8
// baseline (speedup 1.0000x reference)
#include <cuda_runtime.h>
#include <cuda_bf16.h>
#include <cstddef>
#include <cstdint>

#define SEQ   2048
#define BATCH 64
#define NIN   256
#define HID   256

// Scratch: x_proj[s][b][h]
__device__ float g_xp[(size_t)SEQ * BATCH * HID];

// ---------------------------------------------------------------------------
// helpers
// ---------------------------------------------------------------------------
__device__ __forceinline__ uint32_t smem_u32(const void* p) {
    uint32_t a;
    asm("{ .reg .u64 t; cvta.to.shared.u64 t, %1; cvt.u32.u64 %0, t; }"
        : "=r"(a) : "l"(p));
    return a;
}

#define FMA2(acc, a, b)                                             \
    asm("fma.rn.f32x2 %0, %1, %2, %3;"                              \
        : "=l"(acc) : "l"(a), "l"(b), "l"(acc))

__device__ __forceinline__ unsigned long long pack_dup(float x) {
    unsigned long long d;
    asm("mov.b64 %0, {%1, %1};" : "=l"(d) : "r"(__float_as_uint(x)));
    return d;
}
__device__ __forceinline__ float2 unpack2(unsigned long long v) {
    float2 r;
    asm("mov.b64 {%0, %1}, %2;" : "=f"(r.x), "=f"(r.y) : "l"(v));
    return r;
}

__device__ __forceinline__ void mbar_wait(uint32_t mbar, uint32_t parity) {
    asm volatile(
        "{\n\t"
        ".reg .pred P;\n"
        "$WL%=:\n\t"
        "mbarrier.try_wait.parity.acquire.cta.shared::cta.b64 P, [%0], %1, 0x989680;\n\t"
        "@!P bra $WL%=;\n\t"
        "}"
        :: "r"(mbar), "r"(parity) : "memory");
}

// fast tanh: 1 - 2/(e^{2x}+1), MUFU-based, ~1e-6 rel err, saturates correctly.
__device__ __forceinline__ float ftanh(float x) {
    float e = __expf(2.f * x);
    return 1.f - __fdividef(2.f, e + 1.f);
}

// ---------------------------------------------------------------------------
// Kernel 1: input projection GEMM (f32x2) — unchanged (R2-proven, ~370us).
// ---------------------------------------------------------------------------
__global__ void __launch_bounds__(256) proj_kernel(
    const float* __restrict__ X,
    const float* __restrict__ W,
    const float* __restrict__ b_ih,
    const float* __restrict__ b_hh)
{
    constexpr int BM = 128, BN = 64, BK = 32;
    __shared__ float As[BK][BM + 4];
    __shared__ float Bs[BK][BN + 4];

    const int tid = threadIdx.x;
    const int m0  = blockIdx.x * BM;
    const int n0  = blockIdx.y * BN;
    const int tx  = tid & 15;
    const int ty  = tid >> 4;

    unsigned long long acc2[4][4];
#pragma unroll
    for (int i = 0; i < 4; i++)
#pragma unroll
        for (int j = 0; j < 4; j++) acc2[i][j] = 0ULL;

    for (int kb = 0; kb < NIN; kb += BK) {
#pragma unroll
        for (int it = 0; it < 4; it++) {
            int idx = tid + it * 256;
            int r   = idx >> 3;
            int c4  = idx & 7;
            float4 v = *(const float4*)&X[(size_t)(m0 + r) * NIN + kb + c4 * 4];
            As[c4 * 4 + 0][r] = v.x;
            As[c4 * 4 + 1][r] = v.y;
            As[c4 * 4 + 2][r] = v.z;
            As[c4 * 4 + 3][r] = v.w;
        }
#pragma unroll
        for (int it = 0; it < 2; it++) {
            int idx = tid + it * 256;
            int r   = idx >> 3;
            int c4  = idx & 7;
            float4 v = *(const float4*)&W[(size_t)(n0 + r) * NIN + kb + c4 * 4];
            Bs[c4 * 4 + 0][r] = v.x;
            Bs[c4 * 4 + 1][r] = v.y;
            Bs[c4 * 4 + 2][r] = v.z;
            Bs[c4 * 4 + 3][r] = v.w;
        }
        __syncthreads();

#pragma unroll
        for (int k = 0; k < BK; k++) {
            const ulonglong2* ap = (const ulonglong2*)&As[k][ty * 8];
            ulonglong2 av0 = ap[0];
            ulonglong2 av1 = ap[1];
            float4 bv = *(const float4*)&Bs[k][tx * 4];
            unsigned long long bd0 = pack_dup(bv.x);
            unsigned long long bd1 = pack_dup(bv.y);
            unsigned long long bd2 = pack_dup(bv.z);
            unsigned long long bd3 = pack_dup(bv.w);
            FMA2(acc2[0][0], av0.x, bd0); FMA2(acc2[0][1], av0.x, bd1);
            FMA2(acc2[0][2], av0.x, bd2); FMA2(acc2[0][3], av0.x, bd3);
            FMA2(acc2[1][0], av0.y, bd0); FMA2(acc2[1][1], av0.y, bd1);
            FMA2(acc2[1][2], av0.y, bd2); FMA2(acc2[1][3], av0.y, bd3);
            FMA2(acc2[2][0], av1.x, bd0); FMA2(acc2[2][1], av1.x, bd1);
            FMA2(acc2[2][2], av1.x, bd2); FMA2(acc2[2][3], av1.x, bd3);
            FMA2(acc2[3][0], av1.y, bd0); FMA2(acc2[3][1], av1.y, bd1);
            FMA2(acc2[3][2], av1.y, bd2); FMA2(acc2[3][3], av1.y, bd3);
        }
        __syncthreads();
    }

    const int nbase = n0 + tx * 4;
    float4 bias;
    bias.x = b_ih[nbase + 0] + b_hh[nbase + 0];
    bias.y = b_ih[nbase + 1] + b_hh[nbase + 1];
    bias.z = b_ih[nbase + 2] + b_hh[nbase + 2];
    bias.w = b_ih[nbase + 3] + b_hh[nbase + 3];
#pragma unroll
    for (int mi = 0; mi < 4; mi++) {
        float2 c0 = unpack2(acc2[mi][0]);
        float2 c1 = unpack2(acc2[mi][1]);
        float2 c2 = unpack2(acc2[mi][2]);
        float2 c3 = unpack2(acc2[mi][3]);
        int mA = m0 + ty * 8 + 2 * mi;
        float4 v0 = { c0.x + bias.x, c1.x + bias.y, c2.x + bias.z, c3.x + bias.w };
        float4 v1 = { c0.y + bias.x, c1.y + bias.y, c2.y + bias.z, c3.y + bias.w };
        *(float4*)&g_xp[(size_t)mA * HID + nbase]       = v0;
        *(float4*)&g_xp[(size_t)(mA + 1) * HID + nbase] = v1;
    }
}

// ---------------------------------------------------------------------------
// Kernel 2: recurrence — batched-v4 h-exchange + shfl-pair reduction.
//   64 clusters x 2 CTAs, one batch per cluster. CTA rank r owns output rows
//   [128r,128r+128). Per step:
//     - warp 0 ships last step's 128 local h values to the peer as 32
//       st.async.v4.b32 messages (32 tx events, vs 256 scalar in R2) read
//       from sm_h AFTER the end-of-step barrier -> no staging bar, no fence.
//     - thread t: row = 128r + (t>>1), q = t&1. Dot over local k-chunk
//       [128r + 64q, +64) (no wait), then peer k-chunk [128(1-r)+64q, +64)
//       after the mbarrier wait. Pair-reduce via shfl.bfly(1) -- no sm_ps,
//       no mid-step barrier. q==0 lane does tanh + STS h + STG out.
//   One __syncthreads per step.
// ---------------------------------------------------------------------------
__global__ void __launch_bounds__(256, 1) __cluster_dims__(2, 1, 1)
rnn5_kernel(const float* __restrict__ W_hh, float* __restrict__ out)
{
    __shared__ float sm_h[2][256];   // full h; peer half arrives via st.async.v4
    __shared__ __align__(8) unsigned long long sm_mbar[2];

    const int      t    = threadIdx.x;
    const int      lane = t & 31;
    const uint32_t rank = blockIdx.x & 1;
    const int      b    = blockIdx.x >> 1;

    const int rl   = t >> 1;                                  // local row idx
    const int q    = t & 1;                                   // k-chunk half
    const int row  = (int)(rank << 7) + rl;                   // output row
    const int kc_l = (int)(rank << 7) + (q << 6);             // local h chunk
    const int kc_p = (int)((rank ^ 1u) << 7) + (q << 6);      // peer h chunk

    // weights: W_hh[row][kc_l..+64) and [kc_p..+64) -> 32+32 u64 regs
    unsigned long long wl[32], wp[32];
    {
        const ulonglong2* a = (const ulonglong2*)(W_hh + (size_t)row * HID + kc_l);
        const ulonglong2* c = (const ulonglong2*)(W_hh + (size_t)row * HID + kc_p);
#pragma unroll
        for (int i = 0; i < 16; i++) {
            ulonglong2 v = a[i];
            wl[2 * i] = v.x; wl[2 * i + 1] = v.y;
            ulonglong2 w = c[i];
            wp[2 * i] = w.x; wp[2 * i + 1] = w.y;
        }
    }

    if (t == 0) {
        asm volatile("mbarrier.init.shared.b64 [%0], 1;"
                     :: "r"(smem_u32(&sm_mbar[0])) : "memory");
        asm volatile("mbarrier.init.shared.b64 [%0], 1;"
                     :: "r"(smem_u32(&sm_mbar[1])) : "memory");
    }
    if (t < 256) { /* zero both halves of buffer 0 (sent at s=0) */ }
    sm_h[0][t] = 0.f;
    __syncthreads();
    asm volatile("barrier.cluster.arrive.aligned;" ::: "memory");
    asm volatile("barrier.cluster.wait.aligned;"   ::: "memory");

    // remote addresses (warp 0 sender): lane l ships sm_h[buf][128*rank+4l..+4]
    const uint32_t peer  = rank ^ 1u;
    const uint32_t h_loc = smem_u32(&sm_h[0][0]);
    const uint32_t m_loc = smem_u32(&sm_mbar[0]);
    uint32_t h_rem, m_rem;
    asm("mapa.shared::cluster.u32 %0, %1, %2;"
        : "=r"(h_rem) : "r"(h_loc), "r"(peer));
    asm("mapa.shared::cluster.u32 %0, %1, %2;"
        : "=r"(m_rem) : "r"(m_loc), "r"(peer));
    const uint32_t send_off = (rank << 9) + ((uint32_t)lane << 4); // bytes
    const uint32_t h_rem_sl = h_rem + send_off;
    const uint32_t h_loc_sl = h_loc + send_off;

    // xp window (q==0 lanes combine)
    const float* xptr = g_xp + (size_t)b * HID + row;
    float x0 = 0.f, x1 = 0.f, x2 = 0.f;
    if (q == 0) {
        x0 = xptr[0];
        x1 = xptr[(size_t)1 * BATCH * HID];
        x2 = xptr[(size_t)2 * BATCH * HID];
    }
    float* outp = out + (size_t)b * HID + row;

#pragma unroll 1
    for (int s = 0; s < SEQ; s++) {
        const uint32_t buf = (uint32_t)(s & 1);
        const uint32_t nb  = buf ^ 1u;
        const uint32_t par = (uint32_t)((s >> 1) & 1);

        // ---- this step's receive accounting + batched send (warp 0) ----
        if (t == 0)
            asm volatile("mbarrier.arrive.expect_tx.shared.b64 _, [%0], 512;"
                         :: "r"(m_loc + buf * 8u) : "memory");
        if (t < 32) {
            // read last step's local h (post-barrier data) and ship as v4
            uint32_t v0, v1, v2, v3;
            asm volatile("ld.shared.v4.b32 {%0,%1,%2,%3}, [%4];"
                         : "=r"(v0), "=r"(v1), "=r"(v2), "=r"(v3)
                         : "r"(h_loc_sl + (buf << 10)));
            asm volatile(
                "st.async.shared::cluster.mbarrier::complete_tx::bytes.v4.b32 "
                "[%0], {%1,%2,%3,%4}, [%5];"
                :: "r"(h_rem_sl + (buf << 10)),
                   "r"(v0), "r"(v1), "r"(v2), "r"(v3),
                   "r"(m_rem + buf * 8u)
                : "memory");
        }

        // ---- local k-chunk: 64 floats (16 ulonglong2), no wait ----
        unsigned long long a0 = 0ULL, a1 = 0ULL;
        {
            const ulonglong2* hp = (const ulonglong2*)&sm_h[buf][kc_l];
#pragma unroll
            for (int i = 0; i < 16; i++) {
                ulonglong2 hv = hp[i];
                FMA2(a0, wl[2 * i],     hv.x);
                FMA2(a1, wl[2 * i + 1], hv.y);
            }
        }

        // ---- wait for peer h (flight overlapped send+local chunk) ----
        mbar_wait(m_loc + buf * 8u, par);

        // ---- peer k-chunk: 64 floats ----
        {
            const ulonglong2* hp = (const ulonglong2*)&sm_h[buf][kc_p];
#pragma unroll
            for (int i = 0; i < 16; i++) {
                ulonglong2 hv = hp[i];
                FMA2(a0, wp[2 * i],     hv.x);
                FMA2(a1, wp[2 * i + 1], hv.y);
            }
        }
        float2 f0 = unpack2(a0), f1 = unpack2(a1);
        float mine = (f0.x + f0.y) + (f1.x + f1.y);

        // ---- pair reduction within the warp (q pairs differ in bit 0) ----
        float other = __shfl_xor_sync(0xFFFFFFFFu, mine, 1);
        // deterministic order: q0-part + q1-part
        float full = q ? (other + mine) : (mine + other);

        // ---- combine + publish (q==0 lanes: 128 threads, one per row) ----
        if (q == 0) {
            float hv = ftanh(full + x0);
            sm_h[nb][row] = hv;                       // local half only
            outp[(size_t)s * BATCH * HID] = hv;

            x0 = x1; x1 = x2;
            x2 = (s + 3 < SEQ) ? xptr[(size_t)(s + 3) * BATCH * HID] : 0.f;
        }
        __syncthreads();   // sm_h[nb] local half visible to warp-0 sender + dots
    }

    asm volatile("barrier.cluster.arrive.aligned;" ::: "memory");
    asm volatile("barrier.cluster.wait.aligned;"   ::: "memory");
}

// ---------------------------------------------------------------------------
extern "C" void kernel_launch(void* const* d_in, const int* in_sizes, int n_in,
                              void* d_out, int out_size)
{
    const float* input = (const float*)d_in[0];   // [SEQ, BATCH, NIN]
    const float* W_ih  = (const float*)d_in[1];   // [HID, NIN]
    const float* W_hh  = (const float*)d_in[2];   // [HID, HID]
    const float* b_ih  = (const float*)d_in[3];   // [HID]
    const float* b_hh  = (const float*)d_in[4];   // [HID]
    float* out = (float*)d_out;                   // [SEQ*BATCH, HID]

    // 1) projection (full chip)
    dim3 pgrid((SEQ * BATCH) / 128, HID / 64);
    proj_kernel<<<pgrid, 256>>>(input, W_ih, b_ih, b_hh);

    // 2) recurrence: 64 clusters x 2 CTAs, one batch per cluster
    rnn5_kernel<<<BATCH * 2, 256>>>(W_hh, out);
}

// round 9
// speedup vs baseline: 1.2522x; 1.2522x over previous
#include <cuda_runtime.h>
#include <cuda_bf16.h>
#include <cstddef>
#include <cstdint>

#define SEQ   2048
#define BATCH 64
#define NIN   256
#define HID   256

// Scratch: x_proj[s][b][h]
__device__ float g_xp[(size_t)SEQ * BATCH * HID];

// ---------------------------------------------------------------------------
// helpers
// ---------------------------------------------------------------------------
__device__ __forceinline__ uint32_t smem_u32(const void* p) {
    uint32_t a;
    asm("{ .reg .u64 t; cvta.to.shared.u64 t, %1; cvt.u32.u64 %0, t; }"
        : "=r"(a) : "l"(p));
    return a;
}

#define FMA2(acc, a, b)                                             \
    asm("fma.rn.f32x2 %0, %1, %2, %3;"                              \
        : "=l"(acc) : "l"(a), "l"(b), "l"(acc))

__device__ __forceinline__ unsigned long long pack_dup(float x) {
    unsigned long long d;
    asm("mov.b64 %0, {%1, %1};" : "=l"(d) : "r"(__float_as_uint(x)));
    return d;
}
__device__ __forceinline__ float2 unpack2(unsigned long long v) {
    float2 r;
    asm("mov.b64 {%0, %1}, %2;" : "=f"(r.x), "=f"(r.y) : "l"(v));
    return r;
}

__device__ __forceinline__ void mbar_wait(uint32_t mbar, uint32_t parity) {
    asm volatile(
        "{\n\t"
        ".reg .pred P;\n"
        "$WL%=:\n\t"
        "mbarrier.try_wait.parity.acquire.cta.shared::cta.b64 P, [%0], %1, 0x989680;\n\t"
        "@!P bra $WL%=;\n\t"
        "}"
        :: "r"(mbar), "r"(parity) : "memory");
}

// fast tanh: 1 - 2/(e^{2x}+1), MUFU-based, ~1e-6 rel err, saturates correctly.
__device__ __forceinline__ float ftanh(float x) {
    float e = __expf(2.f * x);
    return 1.f - __fdividef(2.f, e + 1.f);
}

// ---------------------------------------------------------------------------
// Kernel 1: input projection GEMM (f32x2) — unchanged (R2-proven, ~370us).
// ---------------------------------------------------------------------------
__global__ void __launch_bounds__(256) proj_kernel(
    const float* __restrict__ X,
    const float* __restrict__ W,
    const float* __restrict__ b_ih,
    const float* __restrict__ b_hh)
{
    constexpr int BM = 128, BN = 64, BK = 32;
    __shared__ float As[BK][BM + 4];
    __shared__ float Bs[BK][BN + 4];

    const int tid = threadIdx.x;
    const int m0  = blockIdx.x * BM;
    const int n0  = blockIdx.y * BN;
    const int tx  = tid & 15;
    const int ty  = tid >> 4;

    unsigned long long acc2[4][4];
#pragma unroll
    for (int i = 0; i < 4; i++)
#pragma unroll
        for (int j = 0; j < 4; j++) acc2[i][j] = 0ULL;

    for (int kb = 0; kb < NIN; kb += BK) {
#pragma unroll
        for (int it = 0; it < 4; it++) {
            int idx = tid + it * 256;
            int r   = idx >> 3;
            int c4  = idx & 7;
            float4 v = *(const float4*)&X[(size_t)(m0 + r) * NIN + kb + c4 * 4];
            As[c4 * 4 + 0][r] = v.x;
            As[c4 * 4 + 1][r] = v.y;
            As[c4 * 4 + 2][r] = v.z;
            As[c4 * 4 + 3][r] = v.w;
        }
#pragma unroll
        for (int it = 0; it < 2; it++) {
            int idx = tid + it * 256;
            int r   = idx >> 3;
            int c4  = idx & 7;
            float4 v = *(const float4*)&W[(size_t)(n0 + r) * NIN + kb + c4 * 4];
            Bs[c4 * 4 + 0][r] = v.x;
            Bs[c4 * 4 + 1][r] = v.y;
            Bs[c4 * 4 + 2][r] = v.z;
            Bs[c4 * 4 + 3][r] = v.w;
        }
        __syncthreads();

#pragma unroll
        for (int k = 0; k < BK; k++) {
            const ulonglong2* ap = (const ulonglong2*)&As[k][ty * 8];
            ulonglong2 av0 = ap[0];
            ulonglong2 av1 = ap[1];
            float4 bv = *(const float4*)&Bs[k][tx * 4];
            unsigned long long bd0 = pack_dup(bv.x);
            unsigned long long bd1 = pack_dup(bv.y);
            unsigned long long bd2 = pack_dup(bv.z);
            unsigned long long bd3 = pack_dup(bv.w);
            FMA2(acc2[0][0], av0.x, bd0); FMA2(acc2[0][1], av0.x, bd1);
            FMA2(acc2[0][2], av0.x, bd2); FMA2(acc2[0][3], av0.x, bd3);
            FMA2(acc2[1][0], av0.y, bd0); FMA2(acc2[1][1], av0.y, bd1);
            FMA2(acc2[1][2], av0.y, bd2); FMA2(acc2[1][3], av0.y, bd3);
            FMA2(acc2[2][0], av1.x, bd0); FMA2(acc2[2][1], av1.x, bd1);
            FMA2(acc2[2][2], av1.x, bd2); FMA2(acc2[2][3], av1.x, bd3);
            FMA2(acc2[3][0], av1.y, bd0); FMA2(acc2[3][1], av1.y, bd1);
            FMA2(acc2[3][2], av1.y, bd2); FMA2(acc2[3][3], av1.y, bd3);
        }
        __syncthreads();
    }

    const int nbase = n0 + tx * 4;
    float4 bias;
    bias.x = b_ih[nbase + 0] + b_hh[nbase + 0];
    bias.y = b_ih[nbase + 1] + b_hh[nbase + 1];
    bias.z = b_ih[nbase + 2] + b_hh[nbase + 2];
    bias.w = b_ih[nbase + 3] + b_hh[nbase + 3];
#pragma unroll
    for (int mi = 0; mi < 4; mi++) {
        float2 c0 = unpack2(acc2[mi][0]);
        float2 c1 = unpack2(acc2[mi][1]);
        float2 c2 = unpack2(acc2[mi][2]);
        float2 c3 = unpack2(acc2[mi][3]);
        int mA = m0 + ty * 8 + 2 * mi;
        float4 v0 = { c0.x + bias.x, c1.x + bias.y, c2.x + bias.z, c3.x + bias.w };
        float4 v1 = { c0.y + bias.x, c1.y + bias.y, c2.y + bias.z, c3.y + bias.w };
        *(float4*)&g_xp[(size_t)mA * HID + nbase]       = v0;
        *(float4*)&g_xp[(size_t)(mA + 1) * HID + nbase] = v1;
    }
}

// ---------------------------------------------------------------------------
// Kernel 2: recurrence rnn6 — 512 threads/CTA, 4-way k-split, h-exchange.
//   64 clusters x 2 CTAs, one batch per cluster. CTA rank r owns output rows
//   [128r, 128r+128) and holds ALL their weights in registers
//   (512 thr x 32 u64 = 128KB/CTA).
//   Thread t: row = 128r + (t&127), chunk c = t>>7 over 64 k's:
//     c=0,1 -> local h half  [128r + 64c)            (no wait)
//     c=2,3 -> peer  h half  [128(1-r) + 64(c-2))    (after mbar wait)
//   Per SMSP: 2 wait-free warps + 2 waiting warps -> latency hiding.
//   Partials to sm_ps[row][c]; bar; t<128 combines (float4 read, fixed
//   order), tanh, STS local h, 128 scalar st.async h -> peer, STG out; bar.
// ---------------------------------------------------------------------------
__global__ void __launch_bounds__(512, 1) __cluster_dims__(2, 1, 1)
rnn6_kernel(const float* __restrict__ W_hh, float* __restrict__ out)
{
    __shared__ float sm_h[2][256];          // full h; peer half via st.async
    __shared__ __align__(16) float sm_ps[128][4];   // partials [row][chunk]
    __shared__ __align__(8) unsigned long long sm_mbar[2];

    const int      t    = threadIdx.x;
    const int      u    = t & 127;          // local row index
    const int      c    = t >> 7;           // k-chunk 0..3
    const uint32_t rank = blockIdx.x & 1;
    const int      b    = blockIdx.x >> 1;

    const int row = (int)(rank << 7) + u;   // global output row
    const bool peer_chunk = (c >= 2);
    const int  ks = peer_chunk
                  ? (int)((rank ^ 1u) << 7) + ((c - 2) << 6)
                  : (int)(rank << 7) + (c << 6);

    // weights: W_hh[row][ks .. ks+64) -> 32 u64 regs
    unsigned long long w2[32];
    {
        const ulonglong2* wp = (const ulonglong2*)(W_hh + (size_t)row * HID + ks);
#pragma unroll
        for (int i = 0; i < 16; i++) {
            ulonglong2 v = wp[i];
            w2[2 * i]     = v.x;
            w2[2 * i + 1] = v.y;
        }
    }

    if (t == 0) {
        asm volatile("mbarrier.init.shared.b64 [%0], 1;"
                     :: "r"(smem_u32(&sm_mbar[0])) : "memory");
        asm volatile("mbarrier.init.shared.b64 [%0], 1;"
                     :: "r"(smem_u32(&sm_mbar[1])) : "memory");
    }
    if (t < 256) sm_h[0][t] = 0.f;           // h_0 = 0 (both halves)
    __syncthreads();
    asm volatile("barrier.cluster.arrive.aligned;" ::: "memory");
    asm volatile("barrier.cluster.wait.aligned;"   ::: "memory");

    // remote addresses: h[row] -> same offset in peer's sm_h
    const uint32_t peer  = rank ^ 1u;
    const uint32_t h_loc = smem_u32(&sm_h[0][0]);
    const uint32_t m_loc = smem_u32(&sm_mbar[0]);
    uint32_t h_rem, m_rem;
    asm("mapa.shared::cluster.u32 %0, %1, %2;"
        : "=r"(h_rem) : "r"(h_loc), "r"(peer));
    asm("mapa.shared::cluster.u32 %0, %1, %2;"
        : "=r"(m_rem) : "r"(m_loc), "r"(peer));
    const uint32_t h_rem_row = h_rem + ((uint32_t)row << 2);  // + buf*1024

    // prologue: expect + send zero h_0 into bar[0]
    // (consumption schedule: step s waits bar[s&1] with parity (s>>1)&1)
    if (t == 0)
        asm volatile("mbarrier.arrive.expect_tx.shared.b64 _, [%0], 512;"
                     :: "r"(m_loc) : "memory");
    if (t < 128)
        asm volatile(
            "st.async.shared::cluster.mbarrier::complete_tx::bytes.b32 "
            "[%0], %1, [%2];"
            :: "r"(h_rem_row), "r"(0u), "r"(m_rem) : "memory");

    // xp window (combine threads t<128 only)
    const float* xptr = g_xp + (size_t)b * HID + row;
    float x0 = 0.f, x1 = 0.f, x2 = 0.f;
    if (t < 128) {
        x0 = xptr[0];
        x1 = xptr[(size_t)1 * BATCH * HID];
        x2 = xptr[(size_t)2 * BATCH * HID];
    }
    float* outp = out + (size_t)b * HID + row;

#pragma unroll 1
    for (int s = 0; s < SEQ; s++) {
        const uint32_t buf = (uint32_t)(s & 1);
        const uint32_t nb  = buf ^ 1u;
        const uint32_t par = (uint32_t)((s >> 1) & 1);

        // expect tx for NEXT step's receive (proven R7 ordering)
        if (t == 0)
            asm volatile("mbarrier.arrive.expect_tx.shared.b64 _, [%0], 512;"
                         :: "r"(m_loc + nb * 8u) : "memory");

        // peer-chunk warps wait for this step's peer h
        if (peer_chunk)
            mbar_wait(m_loc + buf * 8u, par);

        // ---- dot over this thread's 64-k chunk: 16 LDS.128 + 32 FMA2 ----
        unsigned long long a0 = 0ULL, a1 = 0ULL;
        {
            const ulonglong2* hp = (const ulonglong2*)&sm_h[buf][ks];
#pragma unroll
            for (int i = 0; i < 16; i++) {
                ulonglong2 hv = hp[i];
                FMA2(a0, w2[2 * i],     hv.x);
                FMA2(a1, w2[2 * i + 1], hv.y);
            }
        }
        float2 f0 = unpack2(a0), f1 = unpack2(a1);
        sm_ps[u][c] = (f0.x + f0.y) + (f1.x + f1.y);
        __syncthreads();

        // ---- combine + tanh + publish (threads 0-127) ----
        if (t < 128) {
            float4 pv = *(const float4*)&sm_ps[u][0];
            float sum = (pv.x + pv.y) + (pv.z + pv.w);
            float hv  = ftanh(sum + x0);
            sm_h[nb][row] = hv;                       // local half
            asm volatile(
                "st.async.shared::cluster.mbarrier::complete_tx::bytes.b32 "
                "[%0], %1, [%2];"
                :: "r"(h_rem_row + (nb << 10)),
                   "r"(__float_as_uint(hv)),
                   "r"(m_rem + nb * 8u)
                : "memory");
            outp[(size_t)s * BATCH * HID] = hv;

            x0 = x1; x1 = x2;
            x2 = (s + 3 < SEQ) ? xptr[(size_t)(s + 3) * BATCH * HID] : 0.f;
        }
        __syncthreads();   // sm_h[nb] local half + sm_ps reuse safe
    }

    asm volatile("barrier.cluster.arrive.aligned;" ::: "memory");
    asm volatile("barrier.cluster.wait.aligned;"   ::: "memory");
}

// ---------------------------------------------------------------------------
extern "C" void kernel_launch(void* const* d_in, const int* in_sizes, int n_in,
                              void* d_out, int out_size)
{
    const float* input = (const float*)d_in[0];   // [SEQ, BATCH, NIN]
    const float* W_ih  = (const float*)d_in[1];   // [HID, NIN]
    const float* W_hh  = (const float*)d_in[2];   // [HID, HID]
    const float* b_ih  = (const float*)d_in[3];   // [HID]
    const float* b_hh  = (const float*)d_in[4];   // [HID]
    float* out = (float*)d_out;                   // [SEQ*BATCH, HID]

    // 1) projection (full chip)
    dim3 pgrid((SEQ * BATCH) / 128, HID / 64);
    proj_kernel<<<pgrid, 256>>>(input, W_ih, b_ih, b_hh);

    // 2) recurrence: 64 clusters x 2 CTAs, one batch per cluster, 512 thr
    rnn6_kernel<<<BATCH * 2, 512>>>(W_hh, out);
}